// round 14
// baseline (speedup 1.0000x reference)
#include <cuda_runtime.h>
#include <cuda_fp16.h>
#include <cstdint>

// ---------------- problem constants ----------------
#define NS_PER   12500
#define AEVD     1008
#define KPAD1    1024
#define D1       256
#define D2       192
#define D3       160
#define ENS      8
#define NSPECIES 4
#define TM       128
#define NTILES   98
#define NATOM    50000
#define NSE      32
#define NBLOCKS  (ENS * NTILES * NSPECIES)   // 3136

#define NC1 32    // KPAD1/32
#define NC2 8     // D1/32
#define NC3 6     // D2/32

#define SC_UP   2048.0f
#define SC_DN   (1.0f / 2048.0f)

// ---------------- persistent fp16 plane scratch ----------------
// aev: single fp16 plane; W1: single fp16 plane; W2/W3: fp16 hi plane + lo
// plane (residual x2048). All weights transposed [se][n][k].
__device__ uint16_t g_aevH[(size_t)NATOM * KPAD1];
__device__ uint16_t g_w1H[(size_t)NSE * D1 * KPAD1];
__device__ uint16_t g_w2H[(size_t)NSE * D2 * D1];
__device__ uint16_t g_w2L[(size_t)NSE * D2 * D1];
__device__ uint16_t g_w3H[(size_t)NSE * D3 * D2];
__device__ uint16_t g_w3L[(size_t)NSE * D3 * D2];
__device__ double g_scratch;
__device__ int    g_done;

// ---------------- smem layout (bytes) ----------------
#define RI_OFF   0                          // 128 ints
#define RED_OFF  512                        // 256 floats
#define PL       2048
// L1 staging: 2 stages, each [Ah 10240][Bh 20480] = 30720
#define APL(st)  (PL + (st)*30720)
#define BPL(st)  (PL + (st)*30720 + 10240)
// h planes (fp16 hi + lo*2048) overwrite staging after L1: [128][264] per plane
#define HH       PL
#define HL       (PL + 67584)
// W2/W3 hi+lo 2-stage staging after H region (stride 40, K=32 chunks)
#define WPL(b,p) (PL + 135168 + (b)*30720 + (p)*15360)
#define SMEM_BYTES (PL + 135168 + 61440)    // 198656

// ---------------- helpers ----------------
__device__ __forceinline__ uint32_t cvt2h(float v0, float v1) { // f16x2: v0->lo, v1->hi
    uint32_t r;
    asm("cvt.rn.f16x2.f32 %0, %1, %2;" : "=r"(r) : "f"(v1), "f"(v0));
    return r;
}
__device__ __forceinline__ float h2lo(uint32_t h) {
    __half2 hh = *reinterpret_cast<__half2*>(&h);
    return __half2float(hh.x);
}
__device__ __forceinline__ float h2hi(uint32_t h) {
    __half2 hh = *reinterpret_cast<__half2*>(&h);
    return __half2float(hh.y);
}

__device__ __forceinline__ float celu01(float x) {
    return x > 0.f ? x : 0.1f * (__expf(x * 10.f) - 1.f);
}

// f32-accumulate fp16 MMA
__device__ __forceinline__ void mma16h(float d[4], const uint32_t a[4], const uint32_t b[2]) {
    asm volatile(
        "mma.sync.aligned.m16n8k16.row.col.f32.f16.f16.f32 "
        "{%0,%1,%2,%3},{%4,%5,%6,%7},{%8,%9},{%0,%1,%2,%3};\n"
        : "+f"(d[0]), "+f"(d[1]), "+f"(d[2]), "+f"(d[3])
        : "r"(a[0]), "r"(a[1]), "r"(a[2]), "r"(a[3]), "r"(b[0]), "r"(b[1]));
}
// f16-accumulate fp16 MMA (2x rate) for scaled correction terms
__device__ __forceinline__ void mma16hh(uint32_t d[2], const uint32_t a[4], const uint32_t b[2]) {
    asm volatile(
        "mma.sync.aligned.m16n8k16.row.col.f16.f16.f16.f16 "
        "{%0,%1},{%2,%3,%4,%5},{%6,%7},{%0,%1};\n"
        : "+r"(d[0]), "+r"(d[1])
        : "r"(a[0]), "r"(a[1]), "r"(a[2]), "r"(a[3]), "r"(b[0]), "r"(b[1]));
}

__device__ __forceinline__ void ldm4(uint32_t* r, uint32_t addr) {
    asm volatile("ldmatrix.sync.aligned.m8n8.x4.shared.b16 {%0,%1,%2,%3}, [%4];"
                 : "=r"(r[0]), "=r"(r[1]), "=r"(r[2]), "=r"(r[3]) : "r"(addr));
}
__device__ __forceinline__ void ldm2(uint32_t* r, uint32_t addr) {
    asm volatile("ldmatrix.sync.aligned.m8n8.x2.shared.b16 {%0,%1}, [%2];"
                 : "=r"(r[0]), "=r"(r[1]) : "r"(addr));
}

__device__ __forceinline__ void cp16(uint32_t dst, const void* src, int szbytes) {
    asm volatile("cp.async.ca.shared.global [%0], [%1], 16, %2;\n"
                 :: "r"(dst), "l"(src), "r"(szbytes));
}
#define CP_COMMIT()  asm volatile("cp.async.commit_group;\n" ::)
#define CP_WAIT1()   asm volatile("cp.async.wait_group 1;\n" ::)
#define CP_WAIT0()   asm volatile("cp.async.wait_group 0;\n" ::)

// ---------------- merged pre-pass ----------------
#define T_AEV ((long)NATOM * (KPAD1 / 2))
#define T_W1  ((long)NSE * D1 * (KPAD1 / 2))
#define T_W2  ((long)NSE * D2 * (D1 / 2))
#define T_W3  ((long)NSE * D3 * (D2 / 2))
#define T_ALL (T_AEV + T_W1 + T_W2 + T_W3)

__global__ void prep_all(const float* __restrict__ aev, const float* __restrict__ W1,
                         const float* __restrict__ W2, const float* __restrict__ W3)
{
    long t = (long)blockIdx.x * 256 + threadIdx.x;
    if (t == 0) { g_scratch = 0.0; g_done = 0; }
    if (t >= T_ALL) return;

    if (t < T_AEV) {
        // aev -> single fp16 plane (per-atom random error cancels in the sum)
        long a  = t / (KPAD1 / 2);
        int  kp = (int)(t - a * (KPAD1 / 2));
        int  k  = 2 * kp;
        float v0 = (k     < AEVD) ? aev[(size_t)a * AEVD + k]     : 0.f;
        float v1 = (k + 1 < AEVD) ? aev[(size_t)a * AEVD + k + 1] : 0.f;
        ((uint32_t*)g_aevH)[t] = cvt2h(v0, v1);
        return;
    }
    if (t < T_AEV + T_W1) {
        // W1 -> single fp16 plane (coherent error measured 3.3e-5, acceptable)
        long u = t - T_AEV;
        int n  = (int)(u % D1);
        long r = u / D1;
        int kp = (int)(r % (KPAD1 / 2));
        int se = (int)(r / (KPAD1 / 2));
        int k  = 2 * kp;
        float v0 = (k     < AEVD) ? W1[((size_t)se * AEVD + k) * D1 + n]     : 0.f;
        float v1 = (k + 1 < AEVD) ? W1[((size_t)se * AEVD + k + 1) * D1 + n] : 0.f;
        ((uint32_t*)g_w1H)[((size_t)se * D1 + n) * (KPAD1 / 2) + kp] = cvt2h(v0, v1);
        return;
    }
    // W2/W3 -> fp16 hi plane + residual-x2048 lo plane (coherent error corrected)
    const float* W; uint16_t *dH, *dL; int K, N; long u;
    if (t < T_AEV + T_W1 + T_W2) { u = t - T_AEV - T_W1;        W = W2; dH = g_w2H; dL = g_w2L; K = D1; N = D2; }
    else                         { u = t - T_AEV - T_W1 - T_W2; W = W3; dH = g_w3H; dL = g_w3L; K = D2; N = D3; }
    int n  = (int)(u % N);
    long r = u / N;
    int kp = (int)(r % (K / 2));
    int se = (int)(r / (K / 2));
    int k  = 2 * kp;
    float v0 = W[((size_t)se * K + k) * N + n];
    float v1 = W[((size_t)se * K + k + 1) * N + n];
    uint32_t h = cvt2h(v0, v1);
    uint32_t l = cvt2h((v0 - h2lo(h)) * SC_UP, (v1 - h2hi(h)) * SC_UP);
    size_t di = ((size_t)se * N + n) * (K / 2) + kp;
    ((uint32_t*)dH)[di] = h;
    ((uint32_t*)dL)[di] = l;
}

// ---------------- main fused kernel (256 threads, 2x4 warps; R12 structure) ----------------
__global__ void __launch_bounds__(256, 1)
ani_main(const float* __restrict__ B1, const float* __restrict__ B2,
         const float* __restrict__ B3, const float* __restrict__ W4,
         const float* __restrict__ B4, const int* __restrict__ idx,
         float* __restrict__ out)
{
    extern __shared__ char smc[];
    const uint32_t smem_base = (uint32_t)__cvta_generic_to_shared(smc);
    int*   rowIdx = (int*)(smc + RI_OFF);
    float* red    = (float*)(smc + RED_OFF);

    const int e    = blockIdx.x;
    const int tile = blockIdx.y;
    const int s    = blockIdx.z;
    const int se   = s * ENS + e;

    const int tid  = threadIdx.x;
    const int lane = tid & 31;
    const int warp = tid >> 5;
    const int gid  = lane >> 2;
    const int tig  = lane & 3;
    const int wm   = warp & 1;
    const int wn   = warp >> 1;     // 0..3
    const int mB   = wm * 64;

    const int amrow = (lane & 7) + (lane & 8);
    const int akoff = (lane & 16) >> 1;
    const int bnrow = (lane & 7) + ((lane & 16) >> 1);
    const int bkoff = lane & 8;

    const int tileBase = tile * TM;
    const int valid    = min(TM, NS_PER - tileBase);

    if (tid < TM)
        rowIdx[tid] = (tid < valid) ? idx[s * NS_PER + tileBase + tid] : -1;
    __syncthreads();

    const float* b1g = B1 + (size_t)se * D1;
    const float* b2g = B2 + (size_t)se * D2;
    const float* b3g = B3 + (size_t)se * D3;
    const float* w4g = W4 + (size_t)se * D3;

    // ---------------- cp.async issue helpers ----------------
    auto issueA1 = [&](int kc, int st) {
        #pragma unroll
        for (int it = 0; it < 2; ++it) {
            int t = tid + it * 256;          // 0..511 : 128 rows x 4 segs
            int r   = t >> 2;
            int seg = t & 3;
            int g   = rowIdx[r];
            const uint16_t* src = g_aevH + ((size_t)(g < 0 ? 0 : g) * KPAD1 + kc * 32 + seg * 8);
            cp16(smem_base + APL(st) + (r * 40 + seg * 8) * 2, src, g >= 0 ? 16 : 0);
        }
    };
    auto issueB1 = [&](int kc, int st) {
        #pragma unroll
        for (int it = 0; it < 4; ++it) {
            int t = tid + it * 256;          // 0..1023 : 256 n x 4 segs
            int n   = t >> 2;
            int seg = t & 3;
            cp16(smem_base + BPL(st) + (n * 40 + seg * 8) * 2,
                 g_w1H + ((size_t)(se * D1 + n) * KPAD1 + kc * 32 + seg * 8), 16);
        }
        CP_COMMIT();
    };
    auto issueW2 = [&](int kc, int b) {
        #pragma unroll
        for (int it = 0; it < 6; ++it) {
            int t = tid + it * 256;          // 0..1535 : 2 planes x 192 n x 4 segs
            int p   = t >= 768;
            int rem = t - p * 768;
            int n   = rem >> 2;
            int seg = rem & 3;
            const uint16_t* base = p ? g_w2L : g_w2H;
            cp16(smem_base + WPL(b, p) + (n * 40 + seg * 8) * 2,
                 base + ((size_t)(se * D2 + n) * D1 + kc * 32 + seg * 8), 16);
        }
        CP_COMMIT();
    };
    auto issueW3 = [&](int kc, int b) {
        #pragma unroll
        for (int it = 0; it < 5; ++it) {
            int t = tid + it * 256;          // 0..1279 : 2 planes x 160 n x 4 segs
            int p   = t >= 640;
            int rem = t - p * 640;
            int n   = rem >> 2;
            int seg = rem & 3;
            const uint16_t* base = p ? g_w3L : g_w3H;
            cp16(smem_base + WPL(b, p) + (n * 40 + seg * 8) * 2,
                 base + ((size_t)(se * D3 + n) * D2 + kc * 32 + seg * 8), 16);
        }
        CP_COMMIT();
    };

    // ==================== Layer 1: fp16 1-term, [128 x 1024] @ [1024 x 256] ====================
    {
        const int nB = wn * 64;
        float acc[4][8][4];
        #pragma unroll
        for (int mi = 0; mi < 4; mi++)
            #pragma unroll
            for (int j = 0; j < 8; j++)
                #pragma unroll
                for (int q = 0; q < 4; q++) acc[mi][j][q] = 0.f;

        issueA1(0, 0); issueB1(0, 0);
        for (int kc = 0; kc < NC1; ++kc) {
            const int st = kc & 1;
            if (kc + 1 < NC1) { issueA1(kc + 1, st ^ 1); issueB1(kc + 1, st ^ 1); CP_WAIT1(); }
            else              { CP_WAIT0(); }
            __syncthreads();
            #pragma unroll
            for (int ks = 0; ks < 2; ++ks) {
                const int k0 = ks * 16;
                uint32_t AH[4][4];
                #pragma unroll
                for (int mi = 0; mi < 4; mi++) {
                    uint32_t aaddr = smem_base + APL(st)
                                   + ((mB + mi * 16 + amrow) * 40 + k0 + akoff) * 2;
                    ldm4(AH[mi], aaddr);
                }
                #pragma unroll
                for (int jp = 0; jp < 4; ++jp) {
                    uint32_t baddr = smem_base + BPL(st)
                                   + ((nB + jp * 16 + bnrow) * 40 + k0 + bkoff) * 2;
                    uint32_t BH[4];
                    ldm4(BH, baddr);
                    #pragma unroll
                    for (int mi = 0; mi < 4; mi++) {
                        mma16h(acc[mi][2 * jp],     AH[mi], BH);
                        mma16h(acc[mi][2 * jp + 1], AH[mi], BH + 2);
                    }
                }
            }
            __syncthreads();
        }
        issueW2(0, 0);
        // epilogue: bias + CELU -> fp16 h hi plane + lo(x2048) plane
        #pragma unroll
        for (int mi = 0; mi < 4; mi++) {
            int r0 = mB + mi * 16 + gid;
            int r1 = r0 + 8;
            #pragma unroll
            for (int j = 0; j < 8; j++) {
                int c = nB + j * 8 + tig * 2;
                float bb0 = __ldg(b1g + c), bb1 = __ldg(b1g + c + 1);
                float v00 = celu01(acc[mi][j][0] + bb0);
                float v01 = celu01(acc[mi][j][1] + bb1);
                float v10 = celu01(acc[mi][j][2] + bb0);
                float v11 = celu01(acc[mi][j][3] + bb1);
                uint32_t h0 = cvt2h(v00, v01);
                uint32_t l0 = cvt2h((v00 - h2lo(h0)) * SC_UP, (v01 - h2hi(h0)) * SC_UP);
                uint32_t h1 = cvt2h(v10, v11);
                uint32_t l1 = cvt2h((v10 - h2lo(h1)) * SC_UP, (v11 - h2hi(h1)) * SC_UP);
                *(uint32_t*)(smc + HH + (r0 * 264 + c) * 2) = h0;
                *(uint32_t*)(smc + HL + (r0 * 264 + c) * 2) = l0;
                *(uint32_t*)(smc + HH + (r1 * 264 + c) * 2) = h1;
                *(uint32_t*)(smc + HL + (r1 * 264 + c) * 2) = l1;
            }
        }
    }

    // ==================== Layer 2: [128x256]@[256x192] — f32 main + f16-acc corrections ====================
    {
        const int nB = wn * 48;
        float    acc[4][6][4];
        uint32_t accl[4][6][2];
        #pragma unroll
        for (int mi = 0; mi < 4; mi++)
            #pragma unroll
            for (int j = 0; j < 6; j++) {
                #pragma unroll
                for (int q = 0; q < 4; q++) acc[mi][j][q] = 0.f;
                accl[mi][j][0] = 0u; accl[mi][j][1] = 0u;
            }

        for (int kc = 0; kc < NC2; ++kc) {
            if (kc + 1 < NC2) { issueW2(kc + 1, (kc + 1) & 1); CP_WAIT1(); }
            else              { CP_WAIT0(); }
            __syncthreads();
            const int b = kc & 1;
            #pragma unroll
            for (int ks = 0; ks < 2; ++ks) {
                const int kg0 = kc * 32 + ks * 16;
                uint32_t AH[4][4], AL[4][4];
                #pragma unroll
                for (int mi = 0; mi < 4; mi++) {
                    uint32_t aaddr = smem_base + HH
                                   + ((mB + mi * 16 + amrow) * 264 + kg0 + akoff) * 2;
                    ldm4(AH[mi], aaddr);
                    ldm4(AL[mi], aaddr + 67584);
                }
                #pragma unroll
                for (int jp = 0; jp < 3; ++jp) {
                    uint32_t baddr = smem_base + WPL(b, 0)
                                   + ((nB + jp * 16 + bnrow) * 40 + ks * 16 + bkoff) * 2;
                    uint32_t BH[4], BL[4];
                    ldm4(BH, baddr);
                    ldm4(BL, baddr + 15360);
                    #pragma unroll
                    for (int mi = 0; mi < 4; mi++) {
                        mma16h(acc[mi][2 * jp],      AH[mi], BH);
                        mma16h(acc[mi][2 * jp + 1],  AH[mi], BH + 2);
                        mma16hh(accl[mi][2 * jp],     AL[mi], BH);
                        mma16hh(accl[mi][2 * jp + 1], AL[mi], BH + 2);
                        mma16hh(accl[mi][2 * jp],     AH[mi], BL);
                        mma16hh(accl[mi][2 * jp + 1], AH[mi], BL + 2);
                    }
                }
            }
            __syncthreads();
        }
        issueW3(0, 0);
        // epilogue: combine + bias + CELU -> h2 planes (cols 0..191)
        #pragma unroll
        for (int mi = 0; mi < 4; mi++) {
            int r0 = mB + mi * 16 + gid;
            int r1 = r0 + 8;
            #pragma unroll
            for (int j = 0; j < 6; j++) {
                int c = nB + j * 8 + tig * 2;
                float bb0 = __ldg(b2g + c), bb1 = __ldg(b2g + c + 1);
                uint32_t c0 = accl[mi][j][0], c1 = accl[mi][j][1];
                float v00 = celu01(acc[mi][j][0] + SC_DN * h2lo(c0) + bb0);
                float v01 = celu01(acc[mi][j][1] + SC_DN * h2hi(c0) + bb1);
                float v10 = celu01(acc[mi][j][2] + SC_DN * h2lo(c1) + bb0);
                float v11 = celu01(acc[mi][j][3] + SC_DN * h2hi(c1) + bb1);
                uint32_t h0 = cvt2h(v00, v01);
                uint32_t l0 = cvt2h((v00 - h2lo(h0)) * SC_UP, (v01 - h2hi(h0)) * SC_UP);
                uint32_t h1 = cvt2h(v10, v11);
                uint32_t l1 = cvt2h((v10 - h2lo(h1)) * SC_UP, (v11 - h2hi(h1)) * SC_UP);
                *(uint32_t*)(smc + HH + (r0 * 264 + c) * 2) = h0;
                *(uint32_t*)(smc + HL + (r0 * 264 + c) * 2) = l0;
                *(uint32_t*)(smc + HH + (r1 * 264 + c) * 2) = h1;
                *(uint32_t*)(smc + HL + (r1 * 264 + c) * 2) = l1;
            }
        }
    }

    // ==================== Layer 3: [128x192]@[192x160] — f32 main + f16-acc corrections ====================
    float energy = 0.f;
    {
        const int nB = wn * 40;
        float    acc[4][5][4];
        uint32_t accl[4][5][2];
        #pragma unroll
        for (int mi = 0; mi < 4; mi++)
            #pragma unroll
            for (int j = 0; j < 5; j++) {
                #pragma unroll
                for (int q = 0; q < 4; q++) acc[mi][j][q] = 0.f;
                accl[mi][j][0] = 0u; accl[mi][j][1] = 0u;
            }

        for (int kc = 0; kc < NC3; ++kc) {
            if (kc + 1 < NC3) { issueW3(kc + 1, (kc + 1) & 1); CP_WAIT1(); }
            else              { CP_WAIT0(); }
            __syncthreads();
            const int b = kc & 1;
            #pragma unroll
            for (int ks = 0; ks < 2; ++ks) {
                const int kg0 = kc * 32 + ks * 16;
                uint32_t AH[4][4], AL[4][4];
                #pragma unroll
                for (int mi = 0; mi < 4; mi++) {
                    uint32_t aaddr = smem_base + HH
                                   + ((mB + mi * 16 + amrow) * 264 + kg0 + akoff) * 2;
                    ldm4(AH[mi], aaddr);
                    ldm4(AL[mi], aaddr + 67584);
                }
                #pragma unroll
                for (int jp = 0; jp < 2; ++jp) {
                    uint32_t baddr = smem_base + WPL(b, 0)
                                   + ((nB + jp * 16 + bnrow) * 40 + ks * 16 + bkoff) * 2;
                    uint32_t BH[4], BL[4];
                    ldm4(BH, baddr);
                    ldm4(BL, baddr + 15360);
                    #pragma unroll
                    for (int mi = 0; mi < 4; mi++) {
                        mma16h(acc[mi][2 * jp],      AH[mi], BH);
                        mma16h(acc[mi][2 * jp + 1],  AH[mi], BH + 2);
                        mma16hh(accl[mi][2 * jp],     AL[mi], BH);
                        mma16hh(accl[mi][2 * jp + 1], AL[mi], BH + 2);
                        mma16hh(accl[mi][2 * jp],     AH[mi], BL);
                        mma16hh(accl[mi][2 * jp + 1], AH[mi], BL + 2);
                    }
                }
                {   // j = 4 (single octet) via ldmatrix.x2
                    uint32_t baddr = smem_base + WPL(b, 0)
                                   + ((nB + 32 + (lane & 7)) * 40 + ks * 16 + bkoff) * 2;
                    uint32_t BH[2], BL[2];
                    ldm2(BH, baddr);
                    ldm2(BL, baddr + 15360);
                    #pragma unroll
                    for (int mi = 0; mi < 4; mi++) {
                        mma16h(acc[mi][4],  AH[mi], BH);
                        mma16hh(accl[mi][4], AL[mi], BH);
                        mma16hh(accl[mi][4], AH[mi], BL);
                    }
                }
            }
            __syncthreads();
        }
        // epilogue: combine + bias + CELU, dot with w4, row-masked
        #pragma unroll
        for (int mi = 0; mi < 4; mi++) {
            int r0 = mB + mi * 16 + gid;
            int r1 = r0 + 8;
            #pragma unroll
            for (int j = 0; j < 5; j++) {
                int n = nB + j * 8 + tig * 2;
                float bb0 = __ldg(b3g + n), bb1 = __ldg(b3g + n + 1);
                float w0  = __ldg(w4g + n), w1  = __ldg(w4g + n + 1);
                uint32_t c0 = accl[mi][j][0], c1 = accl[mi][j][1];
                if (r0 < valid)
                    energy += celu01(acc[mi][j][0] + SC_DN * h2lo(c0) + bb0) * w0
                            + celu01(acc[mi][j][1] + SC_DN * h2hi(c0) + bb1) * w1;
                if (r1 < valid)
                    energy += celu01(acc[mi][j][2] + SC_DN * h2lo(c1) + bb0) * w0
                            + celu01(acc[mi][j][3] + SC_DN * h2hi(c1) + bb1) * w1;
            }
        }
    }

    red[tid] = energy;
    __syncthreads();
    #pragma unroll
    for (int st = 128; st > 0; st >>= 1) {
        if (tid < st) red[tid] += red[tid + st];
        __syncthreads();
    }
    if (tid == 0) {
        atomicAdd(&g_scratch, (double)(red[0] + (float)valid * B4[se]));
        __threadfence();
        int done = atomicAdd(&g_done, 1);
        if (done == NBLOCKS - 1)
            out[0] = (float)(g_scratch * (1.0 / ENS));
    }
}

extern "C" void kernel_launch(void* const* d_in, const int* in_sizes, int n_in,
                              void* d_out, int out_size)
{
    // Identify inputs by element count (robust to metadata ordering).
    const float *aev = 0, *W1 = 0, *B1 = 0, *W2 = 0, *B2 = 0,
                *W3 = 0, *B3 = 0, *W4 = 0, *B4 = 0;
    const int *idx = 0;
    int n5120 = 0, n50000 = 0;
    for (int i = 0; i < n_in; ++i) {
        switch (in_sizes[i]) {
            case 50400000: aev = (const float*)d_in[i]; break;
            case 8257536:  W1  = (const float*)d_in[i]; break;
            case 8192:     B1  = (const float*)d_in[i]; break;
            case 1572864:  W2  = (const float*)d_in[i]; break;
            case 6144:     B2  = (const float*)d_in[i]; break;
            case 983040:   W3  = (const float*)d_in[i]; break;
            case 5120:
                if (n5120++ == 0) B3 = (const float*)d_in[i];
                else              W4 = (const float*)d_in[i];
                break;
            case 32:       B4  = (const float*)d_in[i]; break;
            case 50000:
                if (n50000++ == 0) { /* species (unused) */ }
                else idx = (const int*)d_in[i];
                break;
            default: break;
        }
    }

    cudaFuncSetAttribute(ani_main,
                         cudaFuncAttributeMaxDynamicSharedMemorySize, SMEM_BYTES);

    prep_all<<<(int)((T_ALL + 255) / 256), 256>>>(aev, W1, W2, W3);

    dim3 grid(ENS, NTILES, NSPECIES);
    ani_main<<<grid, 256, SMEM_BYTES>>>(B1, B2, B3, W4, B4, idx, (float*)d_out);
}

// round 15
// speedup vs baseline: 1.1493x; 1.1493x over previous
#include <cuda_runtime.h>
#include <cuda_fp16.h>
#include <cstdint>

// ---------------- problem constants ----------------
#define NS_PER   12500
#define AEVD     1008
#define KPAD1    1024
#define D1       256
#define D2       192
#define D3       160
#define ENS      8
#define NSPECIES 4
#define TM       128
#define NTILES   98
#define NATOM    50000
#define NSE      32
#define NBLOCKS  (ENS * NTILES * NSPECIES)   // 3136

#define NC1 32    // KPAD1/32
#define NC2 8     // D1/32
#define NC3 6     // D2/32

#define SC_UP   2048.0f
#define SC_DN   (1.0f / 2048.0f)

// ---------------- persistent fp16 plane scratch ----------------
// aev: single fp16 plane; W1: single fp16 plane; W2/W3: fp16 hi plane + lo
// plane (residual x2048, corrects the coherent weight-rounding bias).
// All weights transposed [se][n][k].
__device__ uint16_t g_aevH[(size_t)NATOM * KPAD1];
__device__ uint16_t g_w1H[(size_t)NSE * D1 * KPAD1];
__device__ uint16_t g_w2H[(size_t)NSE * D2 * D1];
__device__ uint16_t g_w2L[(size_t)NSE * D2 * D1];
__device__ uint16_t g_w3H[(size_t)NSE * D3 * D2];
__device__ uint16_t g_w3L[(size_t)NSE * D3 * D2];
__device__ double g_scratch;
__device__ int    g_done;

// ---------------- smem layout (bytes) ----------------
#define RI_OFF   0                          // 128 ints
#define RED_OFF  512                        // 256 floats
#define PL       2048
// L1 staging: 2 stages, each [Ah 10240][Bh 20480] = 30720
#define APL(st)  (PL + (st)*30720)
#define BPL(st)  (PL + (st)*30720 + 10240)
// h plane (single fp16) overwrites staging after L1: [128][264]
#define HH       PL
// W2/W3 hi+lo 2-stage staging after H region (stride 40, K=32 chunks)
#define WPL(b,p) (PL + 67584 + (b)*30720 + (p)*15360)
#define SMEM_BYTES (PL + 67584 + 61440)     // 131072

// ---------------- helpers ----------------
__device__ __forceinline__ uint32_t cvt2h(float v0, float v1) { // f16x2: v0->lo, v1->hi
    uint32_t r;
    asm("cvt.rn.f16x2.f32 %0, %1, %2;" : "=r"(r) : "f"(v1), "f"(v0));
    return r;
}
__device__ __forceinline__ float h2lo(uint32_t h) {
    __half2 hh = *reinterpret_cast<__half2*>(&h);
    return __half2float(hh.x);
}
__device__ __forceinline__ float h2hi(uint32_t h) {
    __half2 hh = *reinterpret_cast<__half2*>(&h);
    return __half2float(hh.y);
}

__device__ __forceinline__ float celu01(float x) {
    return x > 0.f ? x : 0.1f * (__expf(x * 10.f) - 1.f);
}

// f32-accumulate fp16 MMA
__device__ __forceinline__ void mma16h(float d[4], const uint32_t a[4], const uint32_t b[2]) {
    asm volatile(
        "mma.sync.aligned.m16n8k16.row.col.f32.f16.f16.f32 "
        "{%0,%1,%2,%3},{%4,%5,%6,%7},{%8,%9},{%0,%1,%2,%3};\n"
        : "+f"(d[0]), "+f"(d[1]), "+f"(d[2]), "+f"(d[3])
        : "r"(a[0]), "r"(a[1]), "r"(a[2]), "r"(a[3]), "r"(b[0]), "r"(b[1]));
}
// f16-accumulate fp16 MMA for scaled correction terms (keeps acc regs small)
__device__ __forceinline__ void mma16hh(uint32_t d[2], const uint32_t a[4], const uint32_t b[2]) {
    asm volatile(
        "mma.sync.aligned.m16n8k16.row.col.f16.f16.f16.f16 "
        "{%0,%1},{%2,%3,%4,%5},{%6,%7},{%0,%1};\n"
        : "+r"(d[0]), "+r"(d[1])
        : "r"(a[0]), "r"(a[1]), "r"(a[2]), "r"(a[3]), "r"(b[0]), "r"(b[1]));
}

__device__ __forceinline__ void ldm4(uint32_t* r, uint32_t addr) {
    asm volatile("ldmatrix.sync.aligned.m8n8.x4.shared.b16 {%0,%1,%2,%3}, [%4];"
                 : "=r"(r[0]), "=r"(r[1]), "=r"(r[2]), "=r"(r[3]) : "r"(addr));
}
__device__ __forceinline__ void ldm2(uint32_t* r, uint32_t addr) {
    asm volatile("ldmatrix.sync.aligned.m8n8.x2.shared.b16 {%0,%1}, [%2];"
                 : "=r"(r[0]), "=r"(r[1]) : "r"(addr));
}

__device__ __forceinline__ void cp16(uint32_t dst, const void* src, int szbytes) {
    asm volatile("cp.async.ca.shared.global [%0], [%1], 16, %2;\n"
                 :: "r"(dst), "l"(src), "r"(szbytes));
}
#define CP_COMMIT()  asm volatile("cp.async.commit_group;\n" ::)
#define CP_WAIT1()   asm volatile("cp.async.wait_group 1;\n" ::)
#define CP_WAIT0()   asm volatile("cp.async.wait_group 0;\n" ::)

// ---------------- merged pre-pass ----------------
#define T_AEV ((long)NATOM * (KPAD1 / 2))
#define T_W1  ((long)NSE * D1 * (KPAD1 / 2))
#define T_W2  ((long)NSE * D2 * (D1 / 2))
#define T_W3  ((long)NSE * D3 * (D2 / 2))
#define T_ALL (T_AEV + T_W1 + T_W2 + T_W3)

__global__ void prep_all(const float* __restrict__ aev, const float* __restrict__ W1,
                         const float* __restrict__ W2, const float* __restrict__ W3)
{
    long t = (long)blockIdx.x * 256 + threadIdx.x;
    if (t == 0) { g_scratch = 0.0; g_done = 0; }
    if (t >= T_ALL) return;

    if (t < T_AEV) {
        // aev -> single fp16 plane (per-atom random error cancels in the sum)
        long a  = t / (KPAD1 / 2);
        int  kp = (int)(t - a * (KPAD1 / 2));
        int  k  = 2 * kp;
        float v0 = (k     < AEVD) ? aev[(size_t)a * AEVD + k]     : 0.f;
        float v1 = (k + 1 < AEVD) ? aev[(size_t)a * AEVD + k + 1] : 0.f;
        ((uint32_t*)g_aevH)[t] = cvt2h(v0, v1);
        return;
    }
    if (t < T_AEV + T_W1) {
        // W1 -> single fp16 plane (coherent error measured 3.3e-5, acceptable)
        long u = t - T_AEV;
        int n  = (int)(u % D1);
        long r = u / D1;
        int kp = (int)(r % (KPAD1 / 2));
        int se = (int)(r / (KPAD1 / 2));
        int k  = 2 * kp;
        float v0 = (k     < AEVD) ? W1[((size_t)se * AEVD + k) * D1 + n]     : 0.f;
        float v1 = (k + 1 < AEVD) ? W1[((size_t)se * AEVD + k + 1) * D1 + n] : 0.f;
        ((uint32_t*)g_w1H)[((size_t)se * D1 + n) * (KPAD1 / 2) + kp] = cvt2h(v0, v1);
        return;
    }
    // W2/W3 -> fp16 hi plane + residual-x2048 lo plane (coherent error corrected)
    const float* W; uint16_t *dH, *dL; int K, N; long u;
    if (t < T_AEV + T_W1 + T_W2) { u = t - T_AEV - T_W1;        W = W2; dH = g_w2H; dL = g_w2L; K = D1; N = D2; }
    else                         { u = t - T_AEV - T_W1 - T_W2; W = W3; dH = g_w3H; dL = g_w3L; K = D2; N = D3; }
    int n  = (int)(u % N);
    long r = u / N;
    int kp = (int)(r % (K / 2));
    int se = (int)(r / (K / 2));
    int k  = 2 * kp;
    float v0 = W[((size_t)se * K + k) * N + n];
    float v1 = W[((size_t)se * K + k + 1) * N + n];
    uint32_t h = cvt2h(v0, v1);
    uint32_t l = cvt2h((v0 - h2lo(h)) * SC_UP, (v1 - h2hi(h)) * SC_UP);
    size_t di = ((size_t)se * N + n) * (K / 2) + kp;
    ((uint32_t*)dH)[di] = h;
    ((uint32_t*)dL)[di] = l;
}

// ---------------- main fused kernel (256 threads, 2x4 warps) ----------------
__global__ void __launch_bounds__(256, 1)
ani_main(const float* __restrict__ B1, const float* __restrict__ B2,
         const float* __restrict__ B3, const float* __restrict__ W4,
         const float* __restrict__ B4, const int* __restrict__ idx,
         float* __restrict__ out)
{
    extern __shared__ char smc[];
    const uint32_t smem_base = (uint32_t)__cvta_generic_to_shared(smc);
    int*   rowIdx = (int*)(smc + RI_OFF);
    float* red    = (float*)(smc + RED_OFF);

    const int e    = blockIdx.x;
    const int tile = blockIdx.y;
    const int s    = blockIdx.z;
    const int se   = s * ENS + e;

    const int tid  = threadIdx.x;
    const int lane = tid & 31;
    const int warp = tid >> 5;
    const int gid  = lane >> 2;
    const int tig  = lane & 3;
    const int wm   = warp & 1;
    const int wn   = warp >> 1;     // 0..3
    const int mB   = wm * 64;

    const int amrow = (lane & 7) + (lane & 8);
    const int akoff = (lane & 16) >> 1;
    const int bnrow = (lane & 7) + ((lane & 16) >> 1);
    const int bkoff = lane & 8;

    const int tileBase = tile * TM;
    const int valid    = min(TM, NS_PER - tileBase);

    if (tid < TM)
        rowIdx[tid] = (tid < valid) ? idx[s * NS_PER + tileBase + tid] : -1;
    __syncthreads();

    const float* b1g = B1 + (size_t)se * D1;
    const float* b2g = B2 + (size_t)se * D2;
    const float* b3g = B3 + (size_t)se * D3;
    const float* w4g = W4 + (size_t)se * D3;

    // ---------------- cp.async issue helpers ----------------
    auto issueA1 = [&](int kc, int st) {
        #pragma unroll
        for (int it = 0; it < 2; ++it) {
            int t = tid + it * 256;          // 0..511 : 128 rows x 4 segs
            int r   = t >> 2;
            int seg = t & 3;
            int g   = rowIdx[r];
            const uint16_t* src = g_aevH + ((size_t)(g < 0 ? 0 : g) * KPAD1 + kc * 32 + seg * 8);
            cp16(smem_base + APL(st) + (r * 40 + seg * 8) * 2, src, g >= 0 ? 16 : 0);
        }
    };
    auto issueB1 = [&](int kc, int st) {
        #pragma unroll
        for (int it = 0; it < 4; ++it) {
            int t = tid + it * 256;          // 0..1023 : 256 n x 4 segs
            int n   = t >> 2;
            int seg = t & 3;
            cp16(smem_base + BPL(st) + (n * 40 + seg * 8) * 2,
                 g_w1H + ((size_t)(se * D1 + n) * KPAD1 + kc * 32 + seg * 8), 16);
        }
        CP_COMMIT();
    };
    auto issueW2 = [&](int kc, int b) {
        #pragma unroll
        for (int it = 0; it < 6; ++it) {
            int t = tid + it * 256;          // 0..1535 : 2 planes x 192 n x 4 segs
            int p   = t >= 768;
            int rem = t - p * 768;
            int n   = rem >> 2;
            int seg = rem & 3;
            const uint16_t* base = p ? g_w2L : g_w2H;
            cp16(smem_base + WPL(b, p) + (n * 40 + seg * 8) * 2,
                 base + ((size_t)(se * D2 + n) * D1 + kc * 32 + seg * 8), 16);
        }
        CP_COMMIT();
    };
    auto issueW3 = [&](int kc, int b) {
        #pragma unroll
        for (int it = 0; it < 5; ++it) {
            int t = tid + it * 256;          // 0..1279 : 2 planes x 160 n x 4 segs
            int p   = t >= 640;
            int rem = t - p * 640;
            int n   = rem >> 2;
            int seg = rem & 3;
            const uint16_t* base = p ? g_w3L : g_w3H;
            cp16(smem_base + WPL(b, p) + (n * 40 + seg * 8) * 2,
                 base + ((size_t)(se * D3 + n) * D2 + kc * 32 + seg * 8), 16);
        }
        CP_COMMIT();
    };

    // ==================== Layer 1: fp16 1-term, [128 x 1024] @ [1024 x 256] ====================
    {
        const int nB = wn * 64;
        float acc[4][8][4];
        #pragma unroll
        for (int mi = 0; mi < 4; mi++)
            #pragma unroll
            for (int j = 0; j < 8; j++)
                #pragma unroll
                for (int q = 0; q < 4; q++) acc[mi][j][q] = 0.f;

        issueA1(0, 0); issueB1(0, 0);
        for (int kc = 0; kc < NC1; ++kc) {
            const int st = kc & 1;
            if (kc + 1 < NC1) { issueA1(kc + 1, st ^ 1); issueB1(kc + 1, st ^ 1); CP_WAIT1(); }
            else              { CP_WAIT0(); }
            __syncthreads();
            #pragma unroll
            for (int ks = 0; ks < 2; ++ks) {
                const int k0 = ks * 16;
                uint32_t AH[4][4];
                #pragma unroll
                for (int mi = 0; mi < 4; mi++) {
                    uint32_t aaddr = smem_base + APL(st)
                                   + ((mB + mi * 16 + amrow) * 40 + k0 + akoff) * 2;
                    ldm4(AH[mi], aaddr);
                }
                #pragma unroll
                for (int jp = 0; jp < 4; ++jp) {
                    uint32_t baddr = smem_base + BPL(st)
                                   + ((nB + jp * 16 + bnrow) * 40 + k0 + bkoff) * 2;
                    uint32_t BH[4];
                    ldm4(BH, baddr);
                    #pragma unroll
                    for (int mi = 0; mi < 4; mi++) {
                        mma16h(acc[mi][2 * jp],     AH[mi], BH);
                        mma16h(acc[mi][2 * jp + 1], AH[mi], BH + 2);
                    }
                }
            }
            __syncthreads();
        }
        issueW2(0, 0);
        // epilogue: bias + CELU -> single fp16 h plane
        #pragma unroll
        for (int mi = 0; mi < 4; mi++) {
            int r0 = mB + mi * 16 + gid;
            int r1 = r0 + 8;
            #pragma unroll
            for (int j = 0; j < 8; j++) {
                int c = nB + j * 8 + tig * 2;
                float bb0 = __ldg(b1g + c), bb1 = __ldg(b1g + c + 1);
                float v00 = celu01(acc[mi][j][0] + bb0);
                float v01 = celu01(acc[mi][j][1] + bb1);
                float v10 = celu01(acc[mi][j][2] + bb0);
                float v11 = celu01(acc[mi][j][3] + bb1);
                *(uint32_t*)(smc + HH + (r0 * 264 + c) * 2) = cvt2h(v00, v01);
                *(uint32_t*)(smc + HH + (r1 * 264 + c) * 2) = cvt2h(v10, v11);
            }
        }
    }

    // ==================== Layer 2: AH·BH (f32) + AH·BL (f16-acc W correction) ====================
    {
        const int nB = wn * 48;
        float    acc[4][6][4];
        uint32_t accl[4][6][2];
        #pragma unroll
        for (int mi = 0; mi < 4; mi++)
            #pragma unroll
            for (int j = 0; j < 6; j++) {
                #pragma unroll
                for (int q = 0; q < 4; q++) acc[mi][j][q] = 0.f;
                accl[mi][j][0] = 0u; accl[mi][j][1] = 0u;
            }

        for (int kc = 0; kc < NC2; ++kc) {
            if (kc + 1 < NC2) { issueW2(kc + 1, (kc + 1) & 1); CP_WAIT1(); }
            else              { CP_WAIT0(); }
            __syncthreads();
            const int b = kc & 1;
            #pragma unroll
            for (int ks = 0; ks < 2; ++ks) {
                const int kg0 = kc * 32 + ks * 16;
                uint32_t AH[4][4];
                #pragma unroll
                for (int mi = 0; mi < 4; mi++) {
                    uint32_t aaddr = smem_base + HH
                                   + ((mB + mi * 16 + amrow) * 264 + kg0 + akoff) * 2;
                    ldm4(AH[mi], aaddr);
                }
                #pragma unroll
                for (int jp = 0; jp < 3; ++jp) {
                    uint32_t baddr = smem_base + WPL(b, 0)
                                   + ((nB + jp * 16 + bnrow) * 40 + ks * 16 + bkoff) * 2;
                    uint32_t BH[4], BL[4];
                    ldm4(BH, baddr);
                    ldm4(BL, baddr + 15360);
                    #pragma unroll
                    for (int mi = 0; mi < 4; mi++) {
                        mma16h(acc[mi][2 * jp],      AH[mi], BH);
                        mma16h(acc[mi][2 * jp + 1],  AH[mi], BH + 2);
                        mma16hh(accl[mi][2 * jp],     AH[mi], BL);
                        mma16hh(accl[mi][2 * jp + 1], AH[mi], BL + 2);
                    }
                }
            }
            __syncthreads();
        }
        issueW3(0, 0);
        // epilogue: combine + bias + CELU -> h2 plane (cols 0..191)
        #pragma unroll
        for (int mi = 0; mi < 4; mi++) {
            int r0 = mB + mi * 16 + gid;
            int r1 = r0 + 8;
            #pragma unroll
            for (int j = 0; j < 6; j++) {
                int c = nB + j * 8 + tig * 2;
                float bb0 = __ldg(b2g + c), bb1 = __ldg(b2g + c + 1);
                uint32_t c0 = accl[mi][j][0], c1 = accl[mi][j][1];
                float v00 = celu01(acc[mi][j][0] + SC_DN * h2lo(c0) + bb0);
                float v01 = celu01(acc[mi][j][1] + SC_DN * h2hi(c0) + bb1);
                float v10 = celu01(acc[mi][j][2] + SC_DN * h2lo(c1) + bb0);
                float v11 = celu01(acc[mi][j][3] + SC_DN * h2hi(c1) + bb1);
                *(uint32_t*)(smc + HH + (r0 * 264 + c) * 2) = cvt2h(v00, v01);
                *(uint32_t*)(smc + HH + (r1 * 264 + c) * 2) = cvt2h(v10, v11);
            }
        }
    }

    // ==================== Layer 3: AH·BH (f32) + AH·BL (f16-acc W correction) ====================
    float energy = 0.f;
    {
        const int nB = wn * 40;
        float    acc[4][5][4];
        uint32_t accl[4][5][2];
        #pragma unroll
        for (int mi = 0; mi < 4; mi++)
            #pragma unroll
            for (int j = 0; j < 5; j++) {
                #pragma unroll
                for (int q = 0; q < 4; q++) acc[mi][j][q] = 0.f;
                accl[mi][j][0] = 0u; accl[mi][j][1] = 0u;
            }

        for (int kc = 0; kc < NC3; ++kc) {
            if (kc + 1 < NC3) { issueW3(kc + 1, (kc + 1) & 1); CP_WAIT1(); }
            else              { CP_WAIT0(); }
            __syncthreads();
            const int b = kc & 1;
            #pragma unroll
            for (int ks = 0; ks < 2; ++ks) {
                const int kg0 = kc * 32 + ks * 16;
                uint32_t AH[4][4];
                #pragma unroll
                for (int mi = 0; mi < 4; mi++) {
                    uint32_t aaddr = smem_base + HH
                                   + ((mB + mi * 16 + amrow) * 264 + kg0 + akoff) * 2;
                    ldm4(AH[mi], aaddr);
                }
                #pragma unroll
                for (int jp = 0; jp < 2; ++jp) {
                    uint32_t baddr = smem_base + WPL(b, 0)
                                   + ((nB + jp * 16 + bnrow) * 40 + ks * 16 + bkoff) * 2;
                    uint32_t BH[4], BL[4];
                    ldm4(BH, baddr);
                    ldm4(BL, baddr + 15360);
                    #pragma unroll
                    for (int mi = 0; mi < 4; mi++) {
                        mma16h(acc[mi][2 * jp],      AH[mi], BH);
                        mma16h(acc[mi][2 * jp + 1],  AH[mi], BH + 2);
                        mma16hh(accl[mi][2 * jp],     AH[mi], BL);
                        mma16hh(accl[mi][2 * jp + 1], AH[mi], BL + 2);
                    }
                }
                {   // j = 4 (single octet) via ldmatrix.x2
                    uint32_t baddr = smem_base + WPL(b, 0)
                                   + ((nB + 32 + (lane & 7)) * 40 + ks * 16 + bkoff) * 2;
                    uint32_t BH[2], BL[2];
                    ldm2(BH, baddr);
                    ldm2(BL, baddr + 15360);
                    #pragma unroll
                    for (int mi = 0; mi < 4; mi++) {
                        mma16h(acc[mi][4],  AH[mi], BH);
                        mma16hh(accl[mi][4], AH[mi], BL);
                    }
                }
            }
            __syncthreads();
        }
        // epilogue: combine + bias + CELU, dot with w4, row-masked
        #pragma unroll
        for (int mi = 0; mi < 4; mi++) {
            int r0 = mB + mi * 16 + gid;
            int r1 = r0 + 8;
            #pragma unroll
            for (int j = 0; j < 5; j++) {
                int n = nB + j * 8 + tig * 2;
                float bb0 = __ldg(b3g + n), bb1 = __ldg(b3g + n + 1);
                float w0  = __ldg(w4g + n), w1  = __ldg(w4g + n + 1);
                uint32_t c0 = accl[mi][j][0], c1 = accl[mi][j][1];
                if (r0 < valid)
                    energy += celu01(acc[mi][j][0] + SC_DN * h2lo(c0) + bb0) * w0
                            + celu01(acc[mi][j][1] + SC_DN * h2hi(c0) + bb1) * w1;
                if (r1 < valid)
                    energy += celu01(acc[mi][j][2] + SC_DN * h2lo(c1) + bb0) * w0
                            + celu01(acc[mi][j][3] + SC_DN * h2hi(c1) + bb1) * w1;
            }
        }
    }

    red[tid] = energy;
    __syncthreads();
    #pragma unroll
    for (int st = 128; st > 0; st >>= 1) {
        if (tid < st) red[tid] += red[tid + st];
        __syncthreads();
    }
    if (tid == 0) {
        atomicAdd(&g_scratch, (double)(red[0] + (float)valid * B4[se]));
        __threadfence();
        int done = atomicAdd(&g_done, 1);
        if (done == NBLOCKS - 1)
            out[0] = (float)(g_scratch * (1.0 / ENS));
    }
}

extern "C" void kernel_launch(void* const* d_in, const int* in_sizes, int n_in,
                              void* d_out, int out_size)
{
    // Identify inputs by element count (robust to metadata ordering).
    const float *aev = 0, *W1 = 0, *B1 = 0, *W2 = 0, *B2 = 0,
                *W3 = 0, *B3 = 0, *W4 = 0, *B4 = 0;
    const int *idx = 0;
    int n5120 = 0, n50000 = 0;
    for (int i = 0; i < n_in; ++i) {
        switch (in_sizes[i]) {
            case 50400000: aev = (const float*)d_in[i]; break;
            case 8257536:  W1  = (const float*)d_in[i]; break;
            case 8192:     B1  = (const float*)d_in[i]; break;
            case 1572864:  W2  = (const float*)d_in[i]; break;
            case 6144:     B2  = (const float*)d_in[i]; break;
            case 983040:   W3  = (const float*)d_in[i]; break;
            case 5120:
                if (n5120++ == 0) B3 = (const float*)d_in[i];
                else              W4 = (const float*)d_in[i];
                break;
            case 32:       B4  = (const float*)d_in[i]; break;
            case 50000:
                if (n50000++ == 0) { /* species (unused) */ }
                else idx = (const int*)d_in[i];
                break;
            default: break;
        }
    }

    cudaFuncSetAttribute(ani_main,
                         cudaFuncAttributeMaxDynamicSharedMemorySize, SMEM_BYTES);

    prep_all<<<(int)((T_ALL + 255) / 256), 256>>>(aev, W1, W2, W3);

    dim3 grid(ENS, NTILES, NSPECIES);
    ani_main<<<grid, 256, SMEM_BYTES>>>(B1, B2, B3, W4, B4, idx, (float*)d_out);
}

// round 16
// speedup vs baseline: 1.2926x; 1.1247x over previous
#include <cuda_runtime.h>
#include <cuda_fp16.h>
#include <cstdint>

// ---------------- problem constants ----------------
#define NS_PER   12500
#define AEVD     1008
#define KPAD1    1024
#define D1       256
#define D2       192
#define D3       160
#define ENS      8
#define NSPECIES 4
#define TM       128
#define NTILES   98
#define NATOM    50000
#define NSE      32
#define NBLOCKS  (ENS * NTILES * NSPECIES)   // 3136

#define NC1 16    // KPAD1/64  (K=64 chunks)
#define NC2 8     // D1/32
#define NC3 6     // D2/32

#define SC_UP   2048.0f
#define SC_DN   (1.0f / 2048.0f)

// ---------------- persistent fp16 plane scratch ----------------
__device__ uint16_t g_aevH[(size_t)NATOM * KPAD1];
__device__ uint16_t g_w1H[(size_t)NSE * D1 * KPAD1];
__device__ uint16_t g_w2H[(size_t)NSE * D2 * D1];
__device__ uint16_t g_w2L[(size_t)NSE * D2 * D1];
__device__ uint16_t g_w3H[(size_t)NSE * D3 * D2];
__device__ uint16_t g_w3L[(size_t)NSE * D3 * D2];
__device__ double g_scratch;
__device__ int    g_done;

// ---------------- smem layout (bytes) ----------------
#define RI_OFF   0                          // 128 ints
#define RED_OFF  512                        // 256 floats
#define PL       2048
// L1 staging (K=64, stride 72): 2 stages, each [A 18432][B 36864] = 55296
#define APL(st)  (PL + (st)*55296)
#define BPL(st)  (PL + (st)*55296 + 18432)
// h plane (single fp16) overwrites staging after L1: [128][264]
#define HH       PL
// W2/W3 hi+lo 2-stage staging after H region (stride 40, K=32 chunks)
#define WPL(b,p) (PL + 67584 + (b)*30720 + (p)*15360)
#define SMEM_BYTES 131072   // max(2048+110592, 2048+67584+61440)

// ---------------- helpers ----------------
__device__ __forceinline__ uint32_t cvt2h(float v0, float v1) { // f16x2: v0->lo, v1->hi
    uint32_t r;
    asm("cvt.rn.f16x2.f32 %0, %1, %2;" : "=r"(r) : "f"(v1), "f"(v0));
    return r;
}
__device__ __forceinline__ float h2lo(uint32_t h) {
    __half2 hh = *reinterpret_cast<__half2*>(&h);
    return __half2float(hh.x);
}
__device__ __forceinline__ float h2hi(uint32_t h) {
    __half2 hh = *reinterpret_cast<__half2*>(&h);
    return __half2float(hh.y);
}

__device__ __forceinline__ float celu01(float x) {
    return x > 0.f ? x : 0.1f * (__expf(x * 10.f) - 1.f);
}

__device__ __forceinline__ void mma16h(float d[4], const uint32_t a[4], const uint32_t b[2]) {
    asm volatile(
        "mma.sync.aligned.m16n8k16.row.col.f32.f16.f16.f32 "
        "{%0,%1,%2,%3},{%4,%5,%6,%7},{%8,%9},{%0,%1,%2,%3};\n"
        : "+f"(d[0]), "+f"(d[1]), "+f"(d[2]), "+f"(d[3])
        : "r"(a[0]), "r"(a[1]), "r"(a[2]), "r"(a[3]), "r"(b[0]), "r"(b[1]));
}
__device__ __forceinline__ void mma16hh(uint32_t d[2], const uint32_t a[4], const uint32_t b[2]) {
    asm volatile(
        "mma.sync.aligned.m16n8k16.row.col.f16.f16.f16.f16 "
        "{%0,%1},{%2,%3,%4,%5},{%6,%7},{%0,%1};\n"
        : "+r"(d[0]), "+r"(d[1])
        : "r"(a[0]), "r"(a[1]), "r"(a[2]), "r"(a[3]), "r"(b[0]), "r"(b[1]));
}

__device__ __forceinline__ void ldm4(uint32_t* r, uint32_t addr) {
    asm volatile("ldmatrix.sync.aligned.m8n8.x4.shared.b16 {%0,%1,%2,%3}, [%4];"
                 : "=r"(r[0]), "=r"(r[1]), "=r"(r[2]), "=r"(r[3]) : "r"(addr));
}
__device__ __forceinline__ void ldm2(uint32_t* r, uint32_t addr) {
    asm volatile("ldmatrix.sync.aligned.m8n8.x2.shared.b16 {%0,%1}, [%2];"
                 : "=r"(r[0]), "=r"(r[1]) : "r"(addr));
}

__device__ __forceinline__ void cp16(uint32_t dst, const void* src, int szbytes) {
    asm volatile("cp.async.ca.shared.global [%0], [%1], 16, %2;\n"
                 :: "r"(dst), "l"(src), "r"(szbytes));
}
#define CP_COMMIT()  asm volatile("cp.async.commit_group;\n" ::)
#define CP_WAIT1()   asm volatile("cp.async.wait_group 1;\n" ::)
#define CP_WAIT0()   asm volatile("cp.async.wait_group 0;\n" ::)

// ---------------- merged pre-pass ----------------
#define T_AEV ((long)NATOM * (KPAD1 / 2))
#define T_W1  ((long)NSE * D1 * (KPAD1 / 2))
#define T_W2  ((long)NSE * D2 * (D1 / 2))
#define T_W3  ((long)NSE * D3 * (D2 / 2))
#define T_ALL (T_AEV + T_W1 + T_W2 + T_W3)

__global__ void prep_all(const float* __restrict__ aev, const float* __restrict__ W1,
                         const float* __restrict__ W2, const float* __restrict__ W3)
{
    long t = (long)blockIdx.x * 256 + threadIdx.x;
    if (t == 0) { g_scratch = 0.0; g_done = 0; }
    if (t >= T_ALL) return;

    if (t < T_AEV) {
        long a  = t / (KPAD1 / 2);
        int  kp = (int)(t - a * (KPAD1 / 2));
        int  k  = 2 * kp;
        float v0 = (k     < AEVD) ? aev[(size_t)a * AEVD + k]     : 0.f;
        float v1 = (k + 1 < AEVD) ? aev[(size_t)a * AEVD + k + 1] : 0.f;
        ((uint32_t*)g_aevH)[t] = cvt2h(v0, v1);
        return;
    }
    if (t < T_AEV + T_W1) {
        long u = t - T_AEV;
        int n  = (int)(u % D1);
        long r = u / D1;
        int kp = (int)(r % (KPAD1 / 2));
        int se = (int)(r / (KPAD1 / 2));
        int k  = 2 * kp;
        float v0 = (k     < AEVD) ? W1[((size_t)se * AEVD + k) * D1 + n]     : 0.f;
        float v1 = (k + 1 < AEVD) ? W1[((size_t)se * AEVD + k + 1) * D1 + n] : 0.f;
        ((uint32_t*)g_w1H)[((size_t)se * D1 + n) * (KPAD1 / 2) + kp] = cvt2h(v0, v1);
        return;
    }
    const float* W; uint16_t *dH, *dL; int K, N; long u;
    if (t < T_AEV + T_W1 + T_W2) { u = t - T_AEV - T_W1;        W = W2; dH = g_w2H; dL = g_w2L; K = D1; N = D2; }
    else                         { u = t - T_AEV - T_W1 - T_W2; W = W3; dH = g_w3H; dL = g_w3L; K = D2; N = D3; }
    int n  = (int)(u % N);
    long r = u / N;
    int kp = (int)(r % (K / 2));
    int se = (int)(r / (K / 2));
    int k  = 2 * kp;
    float v0 = W[((size_t)se * K + k) * N + n];
    float v1 = W[((size_t)se * K + k + 1) * N + n];
    uint32_t h = cvt2h(v0, v1);
    uint32_t l = cvt2h((v0 - h2lo(h)) * SC_UP, (v1 - h2hi(h)) * SC_UP);
    size_t di = ((size_t)se * N + n) * (K / 2) + kp;
    ((uint32_t*)dH)[di] = h;
    ((uint32_t*)dL)[di] = l;
}

// ---------------- main fused kernel (256 threads, 2x4 warps) ----------------
__global__ void __launch_bounds__(256, 1)
ani_main(const float* __restrict__ B1, const float* __restrict__ B2,
         const float* __restrict__ B3, const float* __restrict__ W4,
         const float* __restrict__ B4, const int* __restrict__ idx,
         float* __restrict__ out)
{
    extern __shared__ char smc[];
    const uint32_t smem_base = (uint32_t)__cvta_generic_to_shared(smc);
    int*   rowIdx = (int*)(smc + RI_OFF);
    float* red    = (float*)(smc + RED_OFF);

    const int e    = blockIdx.x;
    const int tile = blockIdx.y;
    const int s    = blockIdx.z;
    const int se   = s * ENS + e;

    const int tid  = threadIdx.x;
    const int lane = tid & 31;
    const int warp = tid >> 5;
    const int gid  = lane >> 2;
    const int tig  = lane & 3;
    const int wm   = warp & 1;
    const int wn   = warp >> 1;     // 0..3
    const int mB   = wm * 64;

    const int amrow = (lane & 7) + (lane & 8);
    const int akoff = (lane & 16) >> 1;
    const int bnrow = (lane & 7) + ((lane & 16) >> 1);
    const int bkoff = lane & 8;

    const int tileBase = tile * TM;
    const int valid    = min(TM, NS_PER - tileBase);

    if (tid < TM)
        rowIdx[tid] = (tid < valid) ? idx[s * NS_PER + tileBase + tid] : -1;
    __syncthreads();

    const float* b1g = B1 + (size_t)se * D1;
    const float* b2g = B2 + (size_t)se * D2;
    const float* b3g = B3 + (size_t)se * D3;
    const float* w4g = W4 + (size_t)se * D3;

    // ---------------- cp.async issue helpers ----------------
    auto issueA1 = [&](int kc, int st) {     // K=64 chunk: 128 rows x 8 segs
        #pragma unroll
        for (int it = 0; it < 4; ++it) {
            int t = tid + it * 256;          // 0..1023
            int r   = t >> 3;
            int seg = t & 7;
            int g   = rowIdx[r];
            const uint16_t* src = g_aevH + ((size_t)(g < 0 ? 0 : g) * KPAD1 + kc * 64 + seg * 8);
            cp16(smem_base + APL(st) + (r * 72 + seg * 8) * 2, src, g >= 0 ? 16 : 0);
        }
    };
    auto issueB1 = [&](int kc, int st) {     // K=64 chunk: 256 n x 8 segs
        #pragma unroll
        for (int it = 0; it < 8; ++it) {
            int t = tid + it * 256;          // 0..2047
            int n   = t >> 3;
            int seg = t & 7;
            cp16(smem_base + BPL(st) + (n * 72 + seg * 8) * 2,
                 g_w1H + ((size_t)(se * D1 + n) * KPAD1 + kc * 64 + seg * 8), 16);
        }
        CP_COMMIT();
    };
    auto issueW2 = [&](int kc, int b) {
        #pragma unroll
        for (int it = 0; it < 6; ++it) {
            int t = tid + it * 256;          // 0..1535 : 2 planes x 192 n x 4 segs
            int p   = t >= 768;
            int rem = t - p * 768;
            int n   = rem >> 2;
            int seg = rem & 3;
            const uint16_t* base = p ? g_w2L : g_w2H;
            cp16(smem_base + WPL(b, p) + (n * 40 + seg * 8) * 2,
                 base + ((size_t)(se * D2 + n) * D1 + kc * 32 + seg * 8), 16);
        }
        CP_COMMIT();
    };
    auto issueW3 = [&](int kc, int b) {
        #pragma unroll
        for (int it = 0; it < 5; ++it) {
            int t = tid + it * 256;          // 0..1279 : 2 planes x 160 n x 4 segs
            int p   = t >= 640;
            int rem = t - p * 640;
            int n   = rem >> 2;
            int seg = rem & 3;
            const uint16_t* base = p ? g_w3L : g_w3H;
            cp16(smem_base + WPL(b, p) + (n * 40 + seg * 8) * 2,
                 base + ((size_t)(se * D3 + n) * D2 + kc * 32 + seg * 8), 16);
        }
        CP_COMMIT();
    };

    // ==================== Layer 1: fp16 1-term, K=64 chunks ====================
    {
        const int nB = wn * 64;
        float acc[4][8][4];
        #pragma unroll
        for (int mi = 0; mi < 4; mi++)
            #pragma unroll
            for (int j = 0; j < 8; j++)
                #pragma unroll
                for (int q = 0; q < 4; q++) acc[mi][j][q] = 0.f;

        issueA1(0, 0); issueB1(0, 0);
        for (int kc = 0; kc < NC1; ++kc) {
            const int st = kc & 1;
            if (kc + 1 < NC1) { issueA1(kc + 1, st ^ 1); issueB1(kc + 1, st ^ 1); CP_WAIT1(); }
            else              { CP_WAIT0(); }
            __syncthreads();
            #pragma unroll
            for (int ks = 0; ks < 4; ++ks) {
                const int k0 = ks * 16;
                uint32_t AH[4][4];
                #pragma unroll
                for (int mi = 0; mi < 4; mi++) {
                    uint32_t aaddr = smem_base + APL(st)
                                   + ((mB + mi * 16 + amrow) * 72 + k0 + akoff) * 2;
                    ldm4(AH[mi], aaddr);
                }
                #pragma unroll
                for (int jp = 0; jp < 4; ++jp) {
                    uint32_t baddr = smem_base + BPL(st)
                                   + ((nB + jp * 16 + bnrow) * 72 + k0 + bkoff) * 2;
                    uint32_t BH[4];
                    ldm4(BH, baddr);
                    #pragma unroll
                    for (int mi = 0; mi < 4; mi++) {
                        mma16h(acc[mi][2 * jp],     AH[mi], BH);
                        mma16h(acc[mi][2 * jp + 1], AH[mi], BH + 2);
                    }
                }
            }
            __syncthreads();
        }
        issueW2(0, 0);
        // epilogue: bias + CELU -> single fp16 h plane
        #pragma unroll
        for (int mi = 0; mi < 4; mi++) {
            int r0 = mB + mi * 16 + gid;
            int r1 = r0 + 8;
            #pragma unroll
            for (int j = 0; j < 8; j++) {
                int c = nB + j * 8 + tig * 2;
                float bb0 = __ldg(b1g + c), bb1 = __ldg(b1g + c + 1);
                float v00 = celu01(acc[mi][j][0] + bb0);
                float v01 = celu01(acc[mi][j][1] + bb1);
                float v10 = celu01(acc[mi][j][2] + bb0);
                float v11 = celu01(acc[mi][j][3] + bb1);
                *(uint32_t*)(smc + HH + (r0 * 264 + c) * 2) = cvt2h(v00, v01);
                *(uint32_t*)(smc + HH + (r1 * 264 + c) * 2) = cvt2h(v10, v11);
            }
        }
    }

    // ==================== Layer 2: AH·BH (f32) + AH·BL (f16-acc W correction) ====================
    {
        const int nB = wn * 48;
        float    acc[4][6][4];
        uint32_t accl[4][6][2];
        #pragma unroll
        for (int mi = 0; mi < 4; mi++)
            #pragma unroll
            for (int j = 0; j < 6; j++) {
                #pragma unroll
                for (int q = 0; q < 4; q++) acc[mi][j][q] = 0.f;
                accl[mi][j][0] = 0u; accl[mi][j][1] = 0u;
            }

        for (int kc = 0; kc < NC2; ++kc) {
            if (kc + 1 < NC2) { issueW2(kc + 1, (kc + 1) & 1); CP_WAIT1(); }
            else              { CP_WAIT0(); }
            __syncthreads();
            const int b = kc & 1;
            #pragma unroll
            for (int ks = 0; ks < 2; ++ks) {
                const int kg0 = kc * 32 + ks * 16;
                uint32_t AH[4][4];
                #pragma unroll
                for (int mi = 0; mi < 4; mi++) {
                    uint32_t aaddr = smem_base + HH
                                   + ((mB + mi * 16 + amrow) * 264 + kg0 + akoff) * 2;
                    ldm4(AH[mi], aaddr);
                }
                #pragma unroll
                for (int jp = 0; jp < 3; ++jp) {
                    uint32_t baddr = smem_base + WPL(b, 0)
                                   + ((nB + jp * 16 + bnrow) * 40 + ks * 16 + bkoff) * 2;
                    uint32_t BH[4], BL[4];
                    ldm4(BH, baddr);
                    ldm4(BL, baddr + 15360);
                    #pragma unroll
                    for (int mi = 0; mi < 4; mi++) {
                        mma16h(acc[mi][2 * jp],      AH[mi], BH);
                        mma16h(acc[mi][2 * jp + 1],  AH[mi], BH + 2);
                        mma16hh(accl[mi][2 * jp],     AH[mi], BL);
                        mma16hh(accl[mi][2 * jp + 1], AH[mi], BL + 2);
                    }
                }
            }
            __syncthreads();
        }
        issueW3(0, 0);
        // epilogue: combine + bias + CELU -> h2 plane (cols 0..191)
        #pragma unroll
        for (int mi = 0; mi < 4; mi++) {
            int r0 = mB + mi * 16 + gid;
            int r1 = r0 + 8;
            #pragma unroll
            for (int j = 0; j < 6; j++) {
                int c = nB + j * 8 + tig * 2;
                float bb0 = __ldg(b2g + c), bb1 = __ldg(b2g + c + 1);
                uint32_t c0 = accl[mi][j][0], c1 = accl[mi][j][1];
                float v00 = celu01(acc[mi][j][0] + SC_DN * h2lo(c0) + bb0);
                float v01 = celu01(acc[mi][j][1] + SC_DN * h2hi(c0) + bb1);
                float v10 = celu01(acc[mi][j][2] + SC_DN * h2lo(c1) + bb0);
                float v11 = celu01(acc[mi][j][3] + SC_DN * h2hi(c1) + bb1);
                *(uint32_t*)(smc + HH + (r0 * 264 + c) * 2) = cvt2h(v00, v01);
                *(uint32_t*)(smc + HH + (r1 * 264 + c) * 2) = cvt2h(v10, v11);
            }
        }
    }

    // ==================== Layer 3: AH·BH (f32) + AH·BL (f16-acc W correction) ====================
    float energy = 0.f;
    {
        const int nB = wn * 40;
        float    acc[4][5][4];
        uint32_t accl[4][5][2];
        #pragma unroll
        for (int mi = 0; mi < 4; mi++)
            #pragma unroll
            for (int j = 0; j < 5; j++) {
                #pragma unroll
                for (int q = 0; q < 4; q++) acc[mi][j][q] = 0.f;
                accl[mi][j][0] = 0u; accl[mi][j][1] = 0u;
            }

        for (int kc = 0; kc < NC3; ++kc) {
            if (kc + 1 < NC3) { issueW3(kc + 1, (kc + 1) & 1); CP_WAIT1(); }
            else              { CP_WAIT0(); }
            __syncthreads();
            const int b = kc & 1;
            #pragma unroll
            for (int ks = 0; ks < 2; ++ks) {
                const int kg0 = kc * 32 + ks * 16;
                uint32_t AH[4][4];
                #pragma unroll
                for (int mi = 0; mi < 4; mi++) {
                    uint32_t aaddr = smem_base + HH
                                   + ((mB + mi * 16 + amrow) * 264 + kg0 + akoff) * 2;
                    ldm4(AH[mi], aaddr);
                }
                #pragma unroll
                for (int jp = 0; jp < 2; ++jp) {
                    uint32_t baddr = smem_base + WPL(b, 0)
                                   + ((nB + jp * 16 + bnrow) * 40 + ks * 16 + bkoff) * 2;
                    uint32_t BH[4], BL[4];
                    ldm4(BH, baddr);
                    ldm4(BL, baddr + 15360);
                    #pragma unroll
                    for (int mi = 0; mi < 4; mi++) {
                        mma16h(acc[mi][2 * jp],      AH[mi], BH);
                        mma16h(acc[mi][2 * jp + 1],  AH[mi], BH + 2);
                        mma16hh(accl[mi][2 * jp],     AH[mi], BL);
                        mma16hh(accl[mi][2 * jp + 1], AH[mi], BL + 2);
                    }
                }
                {   // j = 4 (single octet) via ldmatrix.x2
                    uint32_t baddr = smem_base + WPL(b, 0)
                                   + ((nB + 32 + (lane & 7)) * 40 + ks * 16 + bkoff) * 2;
                    uint32_t BH[2], BL[2];
                    ldm2(BH, baddr);
                    ldm2(BL, baddr + 15360);
                    #pragma unroll
                    for (int mi = 0; mi < 4; mi++) {
                        mma16h(acc[mi][4],  AH[mi], BH);
                        mma16hh(accl[mi][4], AH[mi], BL);
                    }
                }
            }
            __syncthreads();
        }
        // epilogue: combine + bias + CELU, dot with w4, row-masked
        #pragma unroll
        for (int mi = 0; mi < 4; mi++) {
            int r0 = mB + mi * 16 + gid;
            int r1 = r0 + 8;
            #pragma unroll
            for (int j = 0; j < 5; j++) {
                int n = nB + j * 8 + tig * 2;
                float bb0 = __ldg(b3g + n), bb1 = __ldg(b3g + n + 1);
                float w0  = __ldg(w4g + n), w1  = __ldg(w4g + n + 1);
                uint32_t c0 = accl[mi][j][0], c1 = accl[mi][j][1];
                if (r0 < valid)
                    energy += celu01(acc[mi][j][0] + SC_DN * h2lo(c0) + bb0) * w0
                            + celu01(acc[mi][j][1] + SC_DN * h2hi(c0) + bb1) * w1;
                if (r1 < valid)
                    energy += celu01(acc[mi][j][2] + SC_DN * h2lo(c1) + bb0) * w0
                            + celu01(acc[mi][j][3] + SC_DN * h2hi(c1) + bb1) * w1;
            }
        }
    }

    red[tid] = energy;
    __syncthreads();
    #pragma unroll
    for (int st = 128; st > 0; st >>= 1) {
        if (tid < st) red[tid] += red[tid + st];
        __syncthreads();
    }
    if (tid == 0) {
        atomicAdd(&g_scratch, (double)(red[0] + (float)valid * B4[se]));
        __threadfence();
        int done = atomicAdd(&g_done, 1);
        if (done == NBLOCKS - 1)
            out[0] = (float)(g_scratch * (1.0 / ENS));
    }
}

extern "C" void kernel_launch(void* const* d_in, const int* in_sizes, int n_in,
                              void* d_out, int out_size)
{
    // Identify inputs by element count (robust to metadata ordering).
    const float *aev = 0, *W1 = 0, *B1 = 0, *W2 = 0, *B2 = 0,
                *W3 = 0, *B3 = 0, *W4 = 0, *B4 = 0;
    const int *idx = 0;
    int n5120 = 0, n50000 = 0;
    for (int i = 0; i < n_in; ++i) {
        switch (in_sizes[i]) {
            case 50400000: aev = (const float*)d_in[i]; break;
            case 8257536:  W1  = (const float*)d_in[i]; break;
            case 8192:     B1  = (const float*)d_in[i]; break;
            case 1572864:  W2  = (const float*)d_in[i]; break;
            case 6144:     B2  = (const float*)d_in[i]; break;
            case 983040:   W3  = (const float*)d_in[i]; break;
            case 5120:
                if (n5120++ == 0) B3 = (const float*)d_in[i];
                else              W4 = (const float*)d_in[i];
                break;
            case 32:       B4  = (const float*)d_in[i]; break;
            case 50000:
                if (n50000++ == 0) { /* species (unused) */ }
                else idx = (const int*)d_in[i];
                break;
            default: break;
        }
    }

    cudaFuncSetAttribute(ani_main,
                         cudaFuncAttributeMaxDynamicSharedMemorySize, SMEM_BYTES);

    prep_all<<<(int)((T_ALL + 255) / 256), 256>>>(aev, W1, W2, W3);

    dim3 grid(ENS, NTILES, NSPECIES);
    ani_main<<<grid, 256, SMEM_BYTES>>>(B1, B2, B3, W4, B4, idx, (float*)d_out);
}